// round 16
// baseline (speedup 1.0000x reference)
#include <cuda_runtime.h>
#include <cuda_bf16.h>
#include <cstdint>
#include <cstddef>

#define NN 50000
#define NE 400000
#define DD 128
#define RPC 384                    // rows per CTA (2 chunks of 192)
#define CHUNK 192
#define NT_G 768                   // gemm threads (24 warps)

// Scratch (device globals: allocation-free rule)
__device__ float g_K[NN * DD];
__device__ float g_Q[NN * DD];
__device__ float g_V[NN * DD];
__device__ float g_H[NN * DD];
__device__ __nv_bfloat16 g_Bs[8 * 256 * 128];   // split weights: [w][khi|klo][n]
__device__ int   g_is32;

struct OutArgs {
    float*       dst[4];   // dst[0..2] = K,Q,V ; dst[3] = skip accumulator
    const float* bias;     // added to dst[3]
};
struct PrepArgs { const float* W[8]; };

// ---------------------------------------------------------------------------
// int32-vs-int64 edge_index detection (odd 32-bit words all zero => int64).
// ---------------------------------------------------------------------------
__global__ void detect_init_kernel() { g_is32 = 0; }
__global__ void detect_kernel(const unsigned int* __restrict__ w) {
    int i = blockIdx.x * blockDim.x + threadIdx.x;
    if (i >= NE) return;
    if (w[2 * i + 1] != 0u) atomicOr(&g_is32, 1);
}

// ---------------------------------------------------------------------------
// bf16 split: v = hi + lo (+ O(2^-16 |v|))
// ---------------------------------------------------------------------------
__device__ __forceinline__ void split4(float4 v, uint2& hi, uint2& lo) {
    __nv_bfloat16 hx = __float2bfloat16(v.x);
    __nv_bfloat16 hy = __float2bfloat16(v.y);
    __nv_bfloat16 hz = __float2bfloat16(v.z);
    __nv_bfloat16 hw = __float2bfloat16(v.w);
    __nv_bfloat16 lx = __float2bfloat16(v.x - __bfloat162float(hx));
    __nv_bfloat16 ly = __float2bfloat16(v.y - __bfloat162float(hy));
    __nv_bfloat16 lz = __float2bfloat16(v.z - __bfloat162float(hz));
    __nv_bfloat16 lw = __float2bfloat16(v.w - __bfloat162float(hw));
    hi.x = (uint32_t)__bfloat16_as_ushort(hx) | ((uint32_t)__bfloat16_as_ushort(hy) << 16);
    hi.y = (uint32_t)__bfloat16_as_ushort(hz) | ((uint32_t)__bfloat16_as_ushort(hw) << 16);
    lo.x = (uint32_t)__bfloat16_as_ushort(lx) | ((uint32_t)__bfloat16_as_ushort(ly) << 16);
    lo.y = (uint32_t)__bfloat16_as_ushort(lz) | ((uint32_t)__bfloat16_as_ushort(lw) << 16);
}

// ---------------------------------------------------------------------------
// Weight prep: split each W[k][n] (f32) into g_Bs[w]: rows 0..127 = bf16 hi(k),
// rows 128..255 = bf16 lo(k), n contiguous.
// ---------------------------------------------------------------------------
__global__ void __launch_bounds__(256) prep_weights(PrepArgs pa) {
    const int w = blockIdx.x;
    const float* __restrict__ W = pa.W[w];
    __nv_bfloat16* __restrict__ out = g_Bs + (size_t)w * 256 * 128;
    const int t = threadIdx.x;
    #pragma unroll 4
    for (int l = 0; l < 16; l++) {
        int idx = l * 256 + t;
        int k = idx >> 5;
        int c4 = (idx & 31) * 4;
        float4 v = *(const float4*)&W[(size_t)k * DD + c4];
        uint2 hi, lo;
        split4(v, hi, lo);
        *(uint2*)&out[(size_t)k * 128 + c4]         = hi;
        *(uint2*)&out[(size_t)(128 + k) * 128 + c4] = lo;
    }
}

// ---------------------------------------------------------------------------
// HMMA helpers
// ---------------------------------------------------------------------------
__device__ __forceinline__ uint32_t smem_u32(const void* p) {
    uint32_t a;
    asm("{ .reg .u64 t; cvta.to.shared.u64 t, %1; cvt.u32.u64 %0, t; }"
        : "=r"(a) : "l"(p));
    return a;
}

__device__ __forceinline__ void ldsm4(uint32_t* r, uint32_t addr) {
    asm volatile("ldmatrix.sync.aligned.m8n8.x4.shared.b16 {%0,%1,%2,%3}, [%4];"
        : "=r"(r[0]), "=r"(r[1]), "=r"(r[2]), "=r"(r[3]) : "r"(addr));
}
__device__ __forceinline__ void ldsm4t(uint32_t* r, uint32_t addr) {
    asm volatile("ldmatrix.sync.aligned.m8n8.x4.trans.shared.b16 {%0,%1,%2,%3}, [%4];"
        : "=r"(r[0]), "=r"(r[1]), "=r"(r[2]), "=r"(r[3]) : "r"(addr));
}
__device__ __forceinline__ void mma16816(float* d, const uint32_t* a, const uint32_t* b) {
    asm volatile(
        "mma.sync.aligned.m16n8k16.row.col.f32.bf16.bf16.f32 "
        "{%0,%1,%2,%3}, {%4,%5,%6,%7}, {%8,%9}, {%0,%1,%2,%3};"
        : "+f"(d[0]), "+f"(d[1]), "+f"(d[2]), "+f"(d[3])
        : "r"(a[0]), "r"(a[1]), "r"(a[2]), "r"(a[3]), "r"(b[0]), "r"(b[1]));
}

// ---------------------------------------------------------------------------
// SMEM layout (XOR-swizzled, no padding):
//  A_s: 192 rows x 512B (256 bf16: hi k0..127, lo k128..255).
//       addr = r*512 + ((chunk ^ (r&7))<<4) + within ; chunk = byte>>4
//  B_s: 2 buffers, each 256 rows x 256B (128 bf16).
//       addr = k*256 + ((chunk ^ (k&7))<<4)
// ---------------------------------------------------------------------------
#define SM_A     0
#define SM_B0    98304
#define SM_B1    163840
#define SM_BIAS  229376
#define SMEM_BYTES (229376 + 512)

// ---------------------------------------------------------------------------
// Tensor-core (mma.sync bf16x3 split, merged k-loop) 4-way GEMM.
// One CTA = 384 rows (2 chunks of 192), 4 weights = 8 steps; B double-buffered
// via cp.async prefetch; 131 CTAs = ONE wave. 768 threads (24 warps):
// warp tile 32x32: rg = wid%6 (rows), cg = wid/6 (cols).
// ---------------------------------------------------------------------------
__global__ void __launch_bounds__(NT_G, 1) gemm_hmma_kernel(
    const float* __restrict__ A, const __nv_bfloat16* __restrict__ Bsp,
    OutArgs oa, int apply_relu)
{
    extern __shared__ char smem[];
    char* A_s = smem + SM_A;
    float* bias_s = (float*)(smem + SM_BIAS);

    const int t = threadIdx.x;
    const int wid = t >> 5;
    const int ln = t & 31;
    const int rg = wid % 6;        // rows rg*32 .. +31 within chunk
    const int cg = wid / 6;        // cols cg*32 .. +31

    if (t < 128) bias_s[t] = oa.bias[t];

    const uint32_t sbA  = smem_u32(smem + SM_A);
    const uint32_t sbB0 = smem_u32(smem + SM_B0);
    const uint32_t sbB1 = smem_u32(smem + SM_B1);

    // ---- prologue: prefetch B for step 0 (weight 0) into buf0 ----
    {
        const char* src = (const char*)Bsp;
        #pragma unroll
        for (int l = 0; l < 6; l++) {
            int idx = l * NT_G + t;
            if (idx < 4096) {
                int r = idx >> 4, q = idx & 15;
                uint32_t sa = sbB0 + (uint32_t)(r * 256 + ((q ^ (r & 7)) << 4));
                asm volatile("cp.async.cg.shared.global [%0], [%1], 16;"
                             :: "r"(sa), "l"(src + r * 256 + q * 16) : "memory");
            }
        }
        asm volatile("cp.async.commit_group;" ::: "memory");
    }

    // ---- A convert for chunk c: f32 -> relu? -> bf16 split, swizzled ----
    auto convertA = [&](int c) {
        const int row0 = blockIdx.x * RPC + c * CHUNK;
        #pragma unroll 4
        for (int l = 0; l < 8; l++) {
            int idx = l * NT_G + t;          // 6144 float4 tasks
            int r = idx >> 5;
            int c4 = (idx & 31) * 4;
            int grow = row0 + r;
            float4 v = make_float4(0.f, 0.f, 0.f, 0.f);
            if (grow < NN) v = *(const float4*)&A[(size_t)grow * DD + c4];
            if (apply_relu) {
                v.x = fmaxf(v.x, 0.f); v.y = fmaxf(v.y, 0.f);
                v.z = fmaxf(v.z, 0.f); v.w = fmaxf(v.w, 0.f);
            }
            uint2 hi, lo;
            split4(v, hi, lo);
            int qh = c4 >> 3;                 // hi chunk (0..15)
            int off = (c4 & 7) * 2;           // 0 or 8
            int base = r * 512;
            int sw = r & 7;
            *(uint2*)(A_s + base + ((qh ^ sw) << 4) + off)        = hi;
            *(uint2*)(A_s + base + (((qh + 16) ^ sw) << 4) + off) = lo;
        }
    };
    convertA(0);

    // ---- per-lane ldsm bases ----
    const int mat = ln >> 3, rowin = ln & 7;
    // B: per np (col half), chunk q = cg*4 + np*2 + (mat>>1); row = kB + (mat&1)*8 + rowin
    uint32_t b_lane[2];
    #pragma unroll
    for (int np = 0; np < 2; np++) {
        int q = cg * 4 + np * 2 + (mat >> 1);
        b_lane[np] = (uint32_t)((((mat & 1) * 8 + rowin) * 256) + ((q ^ rowin) << 4));
    }
    // A: row rr = rg*32 + mi*16 + (ln&15); chunk q = 2*ks + (ln>>4) (+16 for lo)
    const uint32_t a_row_base = (uint32_t)((rg * 32 + (ln & 15)) * 512);
    const int axor = ln & 7;
    const int ahalf = ln >> 4;

    // ---- 8 steps: s = c*4 + w ----
    for (int s = 0; s < 8; s++) {
        const int c = s >> 2, w = s & 3;
        if (s == 4) convertA(1);

        // prefetch B for step s+1 into the other buffer
        if (s < 7) {
            const char* src = (const char*)Bsp + (size_t)((s + 1) & 3) * 65536;
            uint32_t dbuf = ((s + 1) & 1) ? sbB1 : sbB0;
            #pragma unroll
            for (int l = 0; l < 6; l++) {
                int idx = l * NT_G + t;
                if (idx < 4096) {
                    int r = idx >> 4, q = idx & 15;
                    uint32_t sa = dbuf + (uint32_t)(r * 256 + ((q ^ (r & 7)) << 4));
                    asm volatile("cp.async.cg.shared.global [%0], [%1], 16;"
                                 :: "r"(sa), "l"(src + r * 256 + q * 16) : "memory");
                }
            }
            asm volatile("cp.async.commit_group;" ::: "memory");
            asm volatile("cp.async.wait_group 1;" ::: "memory");
        } else {
            asm volatile("cp.async.wait_group 0;" ::: "memory");
        }
        __syncthreads();   // B(s) visible; A chunk (if rewritten) visible

        const uint32_t bbuf = (s & 1) ? sbB1 : sbB0;

        float ac[2][4][4];
        #pragma unroll
        for (int mi = 0; mi < 2; mi++)
            #pragma unroll
            for (int nt = 0; nt < 4; nt++)
                #pragma unroll
                for (int j = 0; j < 4; j++) ac[mi][nt][j] = 0.f;

        // ---- merged k-loop ----
        #pragma unroll
        for (int ks = 0; ks < 8; ks++) {
            uint32_t ahi[2][4], alo[2][4], bhi[2][4], blo[2][4];
            #pragma unroll
            for (int np = 0; np < 2; np++) {
                ldsm4t(bhi[np], bbuf + b_lane[np] + (uint32_t)(ks * 16 * 256));
                ldsm4t(blo[np], bbuf + b_lane[np] + (uint32_t)((128 + ks * 16) * 256));
            }
            #pragma unroll
            for (int mi = 0; mi < 2; mi++) {
                int qh = 2 * ks + ahalf;
                uint32_t rbase = sbA + a_row_base + (uint32_t)(mi * 16 * 512);
                ldsm4(ahi[mi], rbase + (uint32_t)((qh ^ axor) << 4));
                ldsm4(alo[mi], rbase + (uint32_t)(((qh + 16) ^ axor) << 4));
            }
            #pragma unroll
            for (int mi = 0; mi < 2; mi++)
                #pragma unroll
                for (int np = 0; np < 2; np++) {
                    mma16816(ac[mi][2 * np],     ahi[mi], &bhi[np][0]);
                    mma16816(ac[mi][2 * np + 1], ahi[mi], &bhi[np][2]);
                    mma16816(ac[mi][2 * np],     alo[mi], &bhi[np][0]);
                    mma16816(ac[mi][2 * np + 1], alo[mi], &bhi[np][2]);
                    mma16816(ac[mi][2 * np],     ahi[mi], &blo[np][0]);
                    mma16816(ac[mi][2 * np + 1], ahi[mi], &blo[np][2]);
                }
        }

        // ---- epilogue for (c, w) ----
        float* dst = oa.dst[w];
        const int r_base = blockIdx.x * RPC + c * CHUNK + rg * 32 + (ln >> 2);
        const int c_base = cg * 32 + (ln & 3) * 2;
        const bool add_bias = (w == 3);
        #pragma unroll
        for (int mi = 0; mi < 2; mi++) {
            const int r_m = r_base + mi * 16;
            #pragma unroll
            for (int nt = 0; nt < 4; nt++) {
                const int cc = c_base + nt * 8;
                float b0 = 0.f, b1 = 0.f;
                if (add_bias) { b0 = bias_s[cc]; b1 = bias_s[cc + 1]; }
                if (r_m < NN)
                    *(float2*)&dst[(size_t)r_m * DD + cc] =
                        make_float2(ac[mi][nt][0] + b0, ac[mi][nt][1] + b1);
                if (r_m + 8 < NN)
                    *(float2*)&dst[(size_t)(r_m + 8) * DD + cc] =
                        make_float2(ac[mi][nt][2] + b0, ac[mi][nt][3] + b1);
            }
        }
        __syncthreads();   // all warps done with buf/A_s before overwrite
    }
}

// ---------------------------------------------------------------------------
// Edge kernel: one warp per TWO edges (batched gathers for 2x MLP).
//   eta = sigmoid(K[tgt] + Q[src]); msg = eta * V[src]; red.v4 into out[tgt]
// ---------------------------------------------------------------------------
__global__ void __launch_bounds__(256) edge_kernel(
    const void* __restrict__ edge_index,
    const float* __restrict__ K, const float* __restrict__ Q,
    const float* __restrict__ V, float* __restrict__ out)
{
    int warp = (blockIdx.x * blockDim.x + threadIdx.x) >> 5;
    int e0 = warp * 2;
    if (e0 >= NE) return;
    int lane = threadIdx.x & 31;
    int d0 = lane * 4;

    int src0, tgt0, src1, tgt1;
    if (g_is32) {
        const int* ei = (const int*)edge_index;
        src0 = ei[e0];      src1 = ei[e0 + 1];
        tgt0 = ei[NE + e0]; tgt1 = ei[NE + e0 + 1];
    } else {
        const long long* ei = (const long long*)edge_index;
        src0 = (int)ei[e0];      src1 = (int)ei[e0 + 1];
        tgt0 = (int)ei[NE + e0]; tgt1 = (int)ei[NE + e0 + 1];
    }

    float4 kt0 = *(const float4*)&K[(size_t)tgt0 * DD + d0];
    float4 qs0 = *(const float4*)&Q[(size_t)src0 * DD + d0];
    float4 vs0 = *(const float4*)&V[(size_t)src0 * DD + d0];
    float4 kt1 = *(const float4*)&K[(size_t)tgt1 * DD + d0];
    float4 qs1 = *(const float4*)&Q[(size_t)src1 * DD + d0];
    float4 vs1 = *(const float4*)&V[(size_t)src1 * DD + d0];

    float4 m0, m1;
    m0.x = vs0.x / (1.f + __expf(-(kt0.x + qs0.x)));
    m0.y = vs0.y / (1.f + __expf(-(kt0.y + qs0.y)));
    m0.z = vs0.z / (1.f + __expf(-(kt0.z + qs0.z)));
    m0.w = vs0.w / (1.f + __expf(-(kt0.w + qs0.w)));
    m1.x = vs1.x / (1.f + __expf(-(kt1.x + qs1.x)));
    m1.y = vs1.y / (1.f + __expf(-(kt1.y + qs1.y)));
    m1.z = vs1.z / (1.f + __expf(-(kt1.z + qs1.z)));
    m1.w = vs1.w / (1.f + __expf(-(kt1.w + qs1.w)));

    float* o0 = &out[(size_t)tgt0 * DD + d0];
    asm volatile("red.global.add.v4.f32 [%0], {%1, %2, %3, %4};"
                 :: "l"(o0), "f"(m0.x), "f"(m0.y), "f"(m0.z), "f"(m0.w)
                 : "memory");
    float* o1 = &out[(size_t)tgt1 * DD + d0];
    asm volatile("red.global.add.v4.f32 [%0], {%1, %2, %3, %4};"
                 :: "l"(o1), "f"(m1.x), "f"(m1.y), "f"(m1.z), "f"(m1.w)
                 : "memory");
}

// ---------------------------------------------------------------------------
extern "C" void kernel_launch(void* const* d_in, const int* in_sizes, int n_in,
                              void* d_out, int out_size)
{
    const float* x   = (const float*)d_in[0];
    const void*  ei  = d_in[1];
    const float* Wk1 = (const float*)d_in[2];
    const float* Wq1 = (const float*)d_in[3];
    const float* Wv1 = (const float*)d_in[4];
    const float* Ws1 = (const float*)d_in[5];
    const float* b1  = (const float*)d_in[6];
    const float* Wk2 = (const float*)d_in[7];
    const float* Wq2 = (const float*)d_in[8];
    const float* Wv2 = (const float*)d_in[9];
    const float* Ws2 = (const float*)d_in[10];
    const float* b2  = (const float*)d_in[11];
    float* out = (float*)d_out;

    float *pK, *pQ, *pV, *pH;
    __nv_bfloat16* pBs;
    cudaGetSymbolAddress((void**)&pK, g_K);
    cudaGetSymbolAddress((void**)&pQ, g_Q);
    cudaGetSymbolAddress((void**)&pV, g_V);
    cudaGetSymbolAddress((void**)&pH, g_H);
    cudaGetSymbolAddress((void**)&pBs, g_Bs);

    cudaFuncSetAttribute(gemm_hmma_kernel,
                         cudaFuncAttributeMaxDynamicSharedMemorySize, SMEM_BYTES);

    detect_init_kernel<<<1, 1>>>();
    detect_kernel<<<(NE + 255) / 256, 256>>>((const unsigned int*)ei);

    PrepArgs pa;
    pa.W[0] = Wk1; pa.W[1] = Wq1; pa.W[2] = Wv1; pa.W[3] = Ws1;
    pa.W[4] = Wk2; pa.W[5] = Wq2; pa.W[6] = Wv2; pa.W[7] = Ws2;
    prep_weights<<<8, 256>>>(pa);

    dim3 ggrid((NN + RPC - 1) / RPC);        // 131 CTAs = one wave
    dim3 egrid((NE / 2 * 32 + 255) / 256);   // one warp per 2 edges

    // ---- Layer 1 ----
    OutArgs o1;
    o1.dst[0] = pK; o1.dst[1] = pQ; o1.dst[2] = pV; o1.dst[3] = pH;
    o1.bias = b1;
    gemm_hmma_kernel<<<ggrid, NT_G, SMEM_BYTES>>>(x, pBs, o1, /*relu=*/0);
    edge_kernel<<<egrid, 256>>>(ei, pK, pQ, pV, pH);

    // ---- Layer 2 (ReLU fused into A convert) ----
    OutArgs o2;
    o2.dst[0] = pK; o2.dst[1] = pQ; o2.dst[2] = pV; o2.dst[3] = out;
    o2.bias = b2;
    gemm_hmma_kernel<<<ggrid, NT_G, SMEM_BYTES>>>(pH, pBs + (size_t)4 * 256 * 128, o2, /*relu=*/1);
    edge_kernel<<<egrid, 256>>>(ei, pK, pQ, pV, out);
}

// round 17
// speedup vs baseline: 1.0010x; 1.0010x over previous
#include <cuda_runtime.h>
#include <cuda_bf16.h>
#include <cstdint>
#include <cstddef>

#define NN 50000
#define NE 400000
#define DD 128
#define RPC 384                    // rows per CTA (2 chunks of 192)
#define CHUNK 192
#define NT_G 768                   // gemm threads (24 warps)

// Scratch (device globals: allocation-free rule)
__device__ float g_K[NN * DD];
__device__ float g_Q[NN * DD];
__device__ float g_V[NN * DD];
__device__ float g_H[NN * DD];
__device__ __nv_bfloat16 g_Bs[8 * 256 * 128];   // split weights: [w][khi|klo][n]
__device__ int   g_is32;

struct OutArgs {
    float*       dst[4];   // dst[0..2] = K,Q,V ; dst[3] = skip accumulator
    const float* bias;     // added to dst[3]
};
struct PrepArgs { const float* W[8]; };

// ---------------------------------------------------------------------------
// int32-vs-int64 edge_index detection (odd 32-bit words all zero => int64).
// ---------------------------------------------------------------------------
__global__ void detect_init_kernel() { g_is32 = 0; }
__global__ void detect_kernel(const unsigned int* __restrict__ w) {
    int i = blockIdx.x * blockDim.x + threadIdx.x;
    if (i >= NE) return;
    if (w[2 * i + 1] != 0u) atomicOr(&g_is32, 1);
}

// ---------------------------------------------------------------------------
// bf16 split: v = hi + lo (+ O(2^-16 |v|))
// ---------------------------------------------------------------------------
__device__ __forceinline__ void split4(float4 v, uint2& hi, uint2& lo) {
    __nv_bfloat16 hx = __float2bfloat16(v.x);
    __nv_bfloat16 hy = __float2bfloat16(v.y);
    __nv_bfloat16 hz = __float2bfloat16(v.z);
    __nv_bfloat16 hw = __float2bfloat16(v.w);
    __nv_bfloat16 lx = __float2bfloat16(v.x - __bfloat162float(hx));
    __nv_bfloat16 ly = __float2bfloat16(v.y - __bfloat162float(hy));
    __nv_bfloat16 lz = __float2bfloat16(v.z - __bfloat162float(hz));
    __nv_bfloat16 lw = __float2bfloat16(v.w - __bfloat162float(hw));
    hi.x = (uint32_t)__bfloat16_as_ushort(hx) | ((uint32_t)__bfloat16_as_ushort(hy) << 16);
    hi.y = (uint32_t)__bfloat16_as_ushort(hz) | ((uint32_t)__bfloat16_as_ushort(hw) << 16);
    lo.x = (uint32_t)__bfloat16_as_ushort(lx) | ((uint32_t)__bfloat16_as_ushort(ly) << 16);
    lo.y = (uint32_t)__bfloat16_as_ushort(lz) | ((uint32_t)__bfloat16_as_ushort(lw) << 16);
}

// ---------------------------------------------------------------------------
// Weight prep: split each W[k][n] (f32) into g_Bs[w]: rows 0..127 = bf16 hi(k),
// rows 128..255 = bf16 lo(k), n contiguous.
// ---------------------------------------------------------------------------
__global__ void __launch_bounds__(256) prep_weights(PrepArgs pa) {
    const int w = blockIdx.x;
    const float* __restrict__ W = pa.W[w];
    __nv_bfloat16* __restrict__ out = g_Bs + (size_t)w * 256 * 128;
    const int t = threadIdx.x;
    #pragma unroll 4
    for (int l = 0; l < 16; l++) {
        int idx = l * 256 + t;
        int k = idx >> 5;
        int c4 = (idx & 31) * 4;
        float4 v = *(const float4*)&W[(size_t)k * DD + c4];
        uint2 hi, lo;
        split4(v, hi, lo);
        *(uint2*)&out[(size_t)k * 128 + c4]         = hi;
        *(uint2*)&out[(size_t)(128 + k) * 128 + c4] = lo;
    }
}

// ---------------------------------------------------------------------------
// HMMA helpers
// ---------------------------------------------------------------------------
__device__ __forceinline__ uint32_t smem_u32(const void* p) {
    uint32_t a;
    asm("{ .reg .u64 t; cvta.to.shared.u64 t, %1; cvt.u32.u64 %0, t; }"
        : "=r"(a) : "l"(p));
    return a;
}

__device__ __forceinline__ void ldsm4(uint32_t* r, uint32_t addr) {
    asm volatile("ldmatrix.sync.aligned.m8n8.x4.shared.b16 {%0,%1,%2,%3}, [%4];"
        : "=r"(r[0]), "=r"(r[1]), "=r"(r[2]), "=r"(r[3]) : "r"(addr));
}
__device__ __forceinline__ void ldsm4t(uint32_t* r, uint32_t addr) {
    asm volatile("ldmatrix.sync.aligned.m8n8.x4.trans.shared.b16 {%0,%1,%2,%3}, [%4];"
        : "=r"(r[0]), "=r"(r[1]), "=r"(r[2]), "=r"(r[3]) : "r"(addr));
}
__device__ __forceinline__ void mma16816(float* d, const uint32_t* a, const uint32_t* b) {
    asm volatile(
        "mma.sync.aligned.m16n8k16.row.col.f32.bf16.bf16.f32 "
        "{%0,%1,%2,%3}, {%4,%5,%6,%7}, {%8,%9}, {%0,%1,%2,%3};"
        : "+f"(d[0]), "+f"(d[1]), "+f"(d[2]), "+f"(d[3])
        : "r"(a[0]), "r"(a[1]), "r"(a[2]), "r"(a[3]), "r"(b[0]), "r"(b[1]));
}

// ---------------------------------------------------------------------------
// SMEM layout (XOR-swizzled, no padding):
//  A_s: 192 rows x 512B (256 bf16: hi k0..127, lo k128..255).
//       addr = r*512 + ((chunk ^ (r&7))<<4) + within ; chunk = byte>>4
//  B_s: 2 buffers, each 256 rows x 256B (128 bf16).
//       addr = k*256 + ((chunk ^ (k&7))<<4)
// ---------------------------------------------------------------------------
#define SM_A     0
#define SM_B0    98304
#define SM_B1    163840
#define SM_BIAS  229376
#define SMEM_BYTES (229376 + 512)

// ---------------------------------------------------------------------------
// Tensor-core (mma.sync bf16x3 split, merged k-loop) 4-way GEMM.
// One CTA = 384 rows (2 chunks of 192), 4 weights = 8 steps; B double-buffered
// via cp.async prefetch; 131 CTAs = ONE wave. 768 threads (24 warps):
// warp tile 32x32: rg = wid%6 (rows), cg = wid/6 (cols).
// ---------------------------------------------------------------------------
__global__ void __launch_bounds__(NT_G, 1) gemm_hmma_kernel(
    const float* __restrict__ A, const __nv_bfloat16* __restrict__ Bsp,
    OutArgs oa, int apply_relu)
{
    extern __shared__ char smem[];
    char* A_s = smem + SM_A;
    float* bias_s = (float*)(smem + SM_BIAS);

    const int t = threadIdx.x;
    const int wid = t >> 5;
    const int ln = t & 31;
    const int rg = wid % 6;        // rows rg*32 .. +31 within chunk
    const int cg = wid / 6;        // cols cg*32 .. +31

    if (t < 128) bias_s[t] = oa.bias[t];

    const uint32_t sbA  = smem_u32(smem + SM_A);
    const uint32_t sbB0 = smem_u32(smem + SM_B0);
    const uint32_t sbB1 = smem_u32(smem + SM_B1);

    // ---- prologue: prefetch B for step 0 (weight 0) into buf0 ----
    {
        const char* src = (const char*)Bsp;
        #pragma unroll
        for (int l = 0; l < 6; l++) {
            int idx = l * NT_G + t;
            if (idx < 4096) {
                int r = idx >> 4, q = idx & 15;
                uint32_t sa = sbB0 + (uint32_t)(r * 256 + ((q ^ (r & 7)) << 4));
                asm volatile("cp.async.cg.shared.global [%0], [%1], 16;"
                             :: "r"(sa), "l"(src + r * 256 + q * 16) : "memory");
            }
        }
        asm volatile("cp.async.commit_group;" ::: "memory");
    }

    // ---- A convert for chunk c: f32 -> relu? -> bf16 split, swizzled ----
    auto convertA = [&](int c) {
        const int row0 = blockIdx.x * RPC + c * CHUNK;
        #pragma unroll 4
        for (int l = 0; l < 8; l++) {
            int idx = l * NT_G + t;          // 6144 float4 tasks
            int r = idx >> 5;
            int c4 = (idx & 31) * 4;
            int grow = row0 + r;
            float4 v = make_float4(0.f, 0.f, 0.f, 0.f);
            if (grow < NN) v = *(const float4*)&A[(size_t)grow * DD + c4];
            if (apply_relu) {
                v.x = fmaxf(v.x, 0.f); v.y = fmaxf(v.y, 0.f);
                v.z = fmaxf(v.z, 0.f); v.w = fmaxf(v.w, 0.f);
            }
            uint2 hi, lo;
            split4(v, hi, lo);
            int qh = c4 >> 3;                 // hi chunk (0..15)
            int off = (c4 & 7) * 2;           // 0 or 8
            int base = r * 512;
            int sw = r & 7;
            *(uint2*)(A_s + base + ((qh ^ sw) << 4) + off)        = hi;
            *(uint2*)(A_s + base + (((qh + 16) ^ sw) << 4) + off) = lo;
        }
    };
    convertA(0);

    // ---- per-lane ldsm bases ----
    const int mat = ln >> 3, rowin = ln & 7;
    // B: per np (col half), chunk q = cg*4 + np*2 + (mat>>1); row = kB + (mat&1)*8 + rowin
    uint32_t b_lane[2];
    #pragma unroll
    for (int np = 0; np < 2; np++) {
        int q = cg * 4 + np * 2 + (mat >> 1);
        b_lane[np] = (uint32_t)((((mat & 1) * 8 + rowin) * 256) + ((q ^ rowin) << 4));
    }
    // A: row rr = rg*32 + mi*16 + (ln&15); chunk q = 2*ks + (ln>>4) (+16 for lo)
    const uint32_t a_row_base = (uint32_t)((rg * 32 + (ln & 15)) * 512);
    const int axor = ln & 7;
    const int ahalf = ln >> 4;

    // ---- 8 steps: s = c*4 + w ----
    for (int s = 0; s < 8; s++) {
        const int c = s >> 2, w = s & 3;
        if (s == 4) convertA(1);

        // prefetch B for step s+1 into the other buffer
        if (s < 7) {
            const char* src = (const char*)Bsp + (size_t)((s + 1) & 3) * 65536;
            uint32_t dbuf = ((s + 1) & 1) ? sbB1 : sbB0;
            #pragma unroll
            for (int l = 0; l < 6; l++) {
                int idx = l * NT_G + t;
                if (idx < 4096) {
                    int r = idx >> 4, q = idx & 15;
                    uint32_t sa = dbuf + (uint32_t)(r * 256 + ((q ^ (r & 7)) << 4));
                    asm volatile("cp.async.cg.shared.global [%0], [%1], 16;"
                                 :: "r"(sa), "l"(src + r * 256 + q * 16) : "memory");
                }
            }
            asm volatile("cp.async.commit_group;" ::: "memory");
            asm volatile("cp.async.wait_group 1;" ::: "memory");
        } else {
            asm volatile("cp.async.wait_group 0;" ::: "memory");
        }
        __syncthreads();   // B(s) visible; A chunk (if rewritten) visible

        const uint32_t bbuf = (s & 1) ? sbB1 : sbB0;

        float ac[2][4][4];
        #pragma unroll
        for (int mi = 0; mi < 2; mi++)
            #pragma unroll
            for (int nt = 0; nt < 4; nt++)
                #pragma unroll
                for (int j = 0; j < 4; j++) ac[mi][nt][j] = 0.f;

        // ---- merged k-loop ----
        #pragma unroll
        for (int ks = 0; ks < 8; ks++) {
            uint32_t ahi[2][4], alo[2][4], bhi[2][4], blo[2][4];
            #pragma unroll
            for (int np = 0; np < 2; np++) {
                ldsm4t(bhi[np], bbuf + b_lane[np] + (uint32_t)(ks * 16 * 256));
                ldsm4t(blo[np], bbuf + b_lane[np] + (uint32_t)((128 + ks * 16) * 256));
            }
            #pragma unroll
            for (int mi = 0; mi < 2; mi++) {
                int qh = 2 * ks + ahalf;
                uint32_t rbase = sbA + a_row_base + (uint32_t)(mi * 16 * 512);
                ldsm4(ahi[mi], rbase + (uint32_t)((qh ^ axor) << 4));
                ldsm4(alo[mi], rbase + (uint32_t)(((qh + 16) ^ axor) << 4));
            }
            #pragma unroll
            for (int mi = 0; mi < 2; mi++)
                #pragma unroll
                for (int np = 0; np < 2; np++) {
                    mma16816(ac[mi][2 * np],     ahi[mi], &bhi[np][0]);
                    mma16816(ac[mi][2 * np + 1], ahi[mi], &bhi[np][2]);
                    mma16816(ac[mi][2 * np],     alo[mi], &bhi[np][0]);
                    mma16816(ac[mi][2 * np + 1], alo[mi], &bhi[np][2]);
                    mma16816(ac[mi][2 * np],     ahi[mi], &blo[np][0]);
                    mma16816(ac[mi][2 * np + 1], ahi[mi], &blo[np][2]);
                }
        }

        // ---- epilogue for (c, w) ----
        float* dst = oa.dst[w];
        const int r_base = blockIdx.x * RPC + c * CHUNK + rg * 32 + (ln >> 2);
        const int c_base = cg * 32 + (ln & 3) * 2;
        const bool add_bias = (w == 3);
        #pragma unroll
        for (int mi = 0; mi < 2; mi++) {
            const int r_m = r_base + mi * 16;
            #pragma unroll
            for (int nt = 0; nt < 4; nt++) {
                const int cc = c_base + nt * 8;
                float b0 = 0.f, b1 = 0.f;
                if (add_bias) { b0 = bias_s[cc]; b1 = bias_s[cc + 1]; }
                if (r_m < NN)
                    *(float2*)&dst[(size_t)r_m * DD + cc] =
                        make_float2(ac[mi][nt][0] + b0, ac[mi][nt][1] + b1);
                if (r_m + 8 < NN)
                    *(float2*)&dst[(size_t)(r_m + 8) * DD + cc] =
                        make_float2(ac[mi][nt][2] + b0, ac[mi][nt][3] + b1);
            }
        }
        __syncthreads();   // all warps done with buf/A_s before overwrite
    }
}

// ---------------------------------------------------------------------------
// Edge kernel: one warp per TWO edges (batched gathers for 2x MLP).
//   eta = sigmoid(K[tgt] + Q[src]); msg = eta * V[src]; red.v4 into out[tgt]
// ---------------------------------------------------------------------------
__global__ void __launch_bounds__(256) edge_kernel(
    const void* __restrict__ edge_index,
    const float* __restrict__ K, const float* __restrict__ Q,
    const float* __restrict__ V, float* __restrict__ out)
{
    int warp = (blockIdx.x * blockDim.x + threadIdx.x) >> 5;
    int e0 = warp * 2;
    if (e0 >= NE) return;
    int lane = threadIdx.x & 31;
    int d0 = lane * 4;

    int src0, tgt0, src1, tgt1;
    if (g_is32) {
        const int* ei = (const int*)edge_index;
        src0 = ei[e0];      src1 = ei[e0 + 1];
        tgt0 = ei[NE + e0]; tgt1 = ei[NE + e0 + 1];
    } else {
        const long long* ei = (const long long*)edge_index;
        src0 = (int)ei[e0];      src1 = (int)ei[e0 + 1];
        tgt0 = (int)ei[NE + e0]; tgt1 = (int)ei[NE + e0 + 1];
    }

    float4 kt0 = *(const float4*)&K[(size_t)tgt0 * DD + d0];
    float4 qs0 = *(const float4*)&Q[(size_t)src0 * DD + d0];
    float4 vs0 = *(const float4*)&V[(size_t)src0 * DD + d0];
    float4 kt1 = *(const float4*)&K[(size_t)tgt1 * DD + d0];
    float4 qs1 = *(const float4*)&Q[(size_t)src1 * DD + d0];
    float4 vs1 = *(const float4*)&V[(size_t)src1 * DD + d0];

    float4 m0, m1;
    m0.x = vs0.x / (1.f + __expf(-(kt0.x + qs0.x)));
    m0.y = vs0.y / (1.f + __expf(-(kt0.y + qs0.y)));
    m0.z = vs0.z / (1.f + __expf(-(kt0.z + qs0.z)));
    m0.w = vs0.w / (1.f + __expf(-(kt0.w + qs0.w)));
    m1.x = vs1.x / (1.f + __expf(-(kt1.x + qs1.x)));
    m1.y = vs1.y / (1.f + __expf(-(kt1.y + qs1.y)));
    m1.z = vs1.z / (1.f + __expf(-(kt1.z + qs1.z)));
    m1.w = vs1.w / (1.f + __expf(-(kt1.w + qs1.w)));

    float* o0 = &out[(size_t)tgt0 * DD + d0];
    asm volatile("red.global.add.v4.f32 [%0], {%1, %2, %3, %4};"
                 :: "l"(o0), "f"(m0.x), "f"(m0.y), "f"(m0.z), "f"(m0.w)
                 : "memory");
    float* o1 = &out[(size_t)tgt1 * DD + d0];
    asm volatile("red.global.add.v4.f32 [%0], {%1, %2, %3, %4};"
                 :: "l"(o1), "f"(m1.x), "f"(m1.y), "f"(m1.z), "f"(m1.w)
                 : "memory");
}

// ---------------------------------------------------------------------------
extern "C" void kernel_launch(void* const* d_in, const int* in_sizes, int n_in,
                              void* d_out, int out_size)
{
    const float* x   = (const float*)d_in[0];
    const void*  ei  = d_in[1];
    const float* Wk1 = (const float*)d_in[2];
    const float* Wq1 = (const float*)d_in[3];
    const float* Wv1 = (const float*)d_in[4];
    const float* Ws1 = (const float*)d_in[5];
    const float* b1  = (const float*)d_in[6];
    const float* Wk2 = (const float*)d_in[7];
    const float* Wq2 = (const float*)d_in[8];
    const float* Wv2 = (const float*)d_in[9];
    const float* Ws2 = (const float*)d_in[10];
    const float* b2  = (const float*)d_in[11];
    float* out = (float*)d_out;

    float *pK, *pQ, *pV, *pH;
    __nv_bfloat16* pBs;
    cudaGetSymbolAddress((void**)&pK, g_K);
    cudaGetSymbolAddress((void**)&pQ, g_Q);
    cudaGetSymbolAddress((void**)&pV, g_V);
    cudaGetSymbolAddress((void**)&pH, g_H);
    cudaGetSymbolAddress((void**)&pBs, g_Bs);

    cudaFuncSetAttribute(gemm_hmma_kernel,
                         cudaFuncAttributeMaxDynamicSharedMemorySize, SMEM_BYTES);

    detect_init_kernel<<<1, 1>>>();
    detect_kernel<<<(NE + 255) / 256, 256>>>((const unsigned int*)ei);

    PrepArgs pa;
    pa.W[0] = Wk1; pa.W[1] = Wq1; pa.W[2] = Wv1; pa.W[3] = Ws1;
    pa.W[4] = Wk2; pa.W[5] = Wq2; pa.W[6] = Wv2; pa.W[7] = Ws2;
    prep_weights<<<8, 256>>>(pa);

    dim3 ggrid((NN + RPC - 1) / RPC);        // 131 CTAs = one wave
    dim3 egrid((NE / 2 * 32 + 255) / 256);   // one warp per 2 edges

    // ---- Layer 1 ----
    OutArgs o1;
    o1.dst[0] = pK; o1.dst[1] = pQ; o1.dst[2] = pV; o1.dst[3] = pH;
    o1.bias = b1;
    gemm_hmma_kernel<<<ggrid, NT_G, SMEM_BYTES>>>(x, pBs, o1, /*relu=*/0);
    edge_kernel<<<egrid, 256>>>(ei, pK, pQ, pV, pH);

    // ---- Layer 2 (ReLU fused into A convert) ----
    OutArgs o2;
    o2.dst[0] = pK; o2.dst[1] = pQ; o2.dst[2] = pV; o2.dst[3] = out;
    o2.bias = b2;
    gemm_hmma_kernel<<<ggrid, NT_G, SMEM_BYTES>>>(pH, pBs + (size_t)4 * 256 * 128, o2, /*relu=*/1);
    edge_kernel<<<egrid, 256>>>(ei, pK, pQ, pV, out);
}